// round 11
// baseline (speedup 1.0000x reference)
#include <cuda_runtime.h>
#include <stdint.h>
#include <math.h>

// Problem constants (fixed by the dataset)
#define H   128
#define OO  20
#define KI  700
#define BB  256
#define TT  250
#define MTOT (BB * TT)   // 64000

// Scratch for the hoisted input projection: xin[(b*T + t)][h]
__device__ float g_xin[(size_t)MTOT * H];

// ---------------------------------------------------------------------------
// f32x2 packed helpers (sm_103a). fma.rn.f32x2 = two independent rn fp32 FMAs
// in one fma-pipe instruction -> bitwise identical to two fmaf.
// ---------------------------------------------------------------------------
typedef unsigned long long ull;

__device__ __forceinline__ ull pk2(float lo, float hi) {
    ull r;
    asm("mov.b64 %0, {%1, %2};" : "=l"(r) : "f"(lo), "f"(hi));
    return r;
}
__device__ __forceinline__ void upk2(float& lo, float& hi, ull v) {
    asm("mov.b64 {%0, %1}, %2;" : "=f"(lo), "=f"(hi) : "l"(v));
}
__device__ __forceinline__ void ffma2(ull& acc, ull a, ull b) {
    asm("fma.rn.f32x2 %0, %1, %2, %0;" : "+l"(acc) : "l"(a), "l"(b));
}

// cp.async wrappers
__device__ __forceinline__ void cpa4(unsigned int dst, const void* src) {
    asm volatile("cp.async.ca.shared.global [%0], [%1], 4;" :: "r"(dst), "l"(src));
}
__device__ __forceinline__ void cpa16(unsigned int dst, const void* src) {
    asm volatile("cp.async.cg.shared.global [%0], [%1], 16;" :: "r"(dst), "l"(src));
}
__device__ __forceinline__ void cpa_commit() {
    asm volatile("cp.async.commit_group;");
}
__device__ __forceinline__ void cpa_wait_all() {
    asm volatile("cp.async.wait_group 0;");
}

// ---------------------------------------------------------------------------
// Bit-exact transcription of XLA CPU's vectorized expf (Cephes/Eigen pexp).
// ---------------------------------------------------------------------------
__device__ __forceinline__ float xla_expf(float xin_) {
    const float exp_hi = 88.3762626647950f;
    const float exp_lo = -88.3762626647949f;
    const float LOG2EF = 1.44269504088896341f;
    const float C1 = 0.693359375f;
    const float C2 = -2.12194440e-4f;
    const float p0 = 1.9875691500E-4f;
    const float p1 = 1.3981999507E-3f;
    const float p2 = 8.3334519073E-3f;
    const float p3 = 4.1665795894E-2f;
    const float p4 = 1.6666665459E-1f;
    const float p5 = 5.0000001201E-1f;

    float x = fminf(fmaxf(xin_, exp_lo), exp_hi);
    float fx = floorf(__fadd_rn(__fmul_rn(x, LOG2EF), 0.5f));
    float tmp = __fmul_rn(C1, fx);
    float z   = __fmul_rn(C2, fx);
    float xx  = __fsub_rn(x, tmp);
    xx = __fsub_rn(xx, z);
    z = __fmul_rn(xx, xx);
    float y = __fadd_rn(__fmul_rn(xx, p0), p1);
    y = __fadd_rn(__fmul_rn(y, xx), p2);
    y = __fadd_rn(__fmul_rn(y, xx), p3);
    y = __fadd_rn(__fmul_rn(y, xx), p4);
    y = __fadd_rn(__fmul_rn(y, xx), p5);
    y = __fadd_rn(__fmul_rn(y, z), xx);
    y = __fadd_rn(1.0f, y);
    int n = (int)fx;
    float p2n = __int_as_float((n + 127) << 23);
    float r = __fmul_rn(y, p2n);
    return fmaxf(r, xin_);
}

// ---------------------------------------------------------------------------
// Phase 1: xin = x @ w_ih1 + b_ih1   (M=64000, K=700, N=128, strict fp32)
// 256 threads, 128x128 tile, 8x8 micro-tile, cp.async double-buffered smem,
// FFMA2, 2 blocks/SM.  (unchanged from R10)
// ---------------------------------------------------------------------------
#define BM  128
#define BN  128
#define BKK 16
#define NT  44
#define ASTRIDE (BM + 4)

__global__ __launch_bounds__(256, 2)
void gemm_xin_kernel(const float* __restrict__ x,
                     const float* __restrict__ w,
                     const float* __restrict__ bias)
{
    __shared__ float As[2][BKK][ASTRIDE];
    __shared__ float Bs[2][BKK][BN];

    const int tid     = threadIdx.x;
    const int block_m = blockIdx.x * BM;
    const int tn      = tid & 15;
    const int tm      = tid >> 4;

    const int ka = tid & 15, ra = tid >> 4;
    const int brow = tid >> 5, bcol4 = tid & 31;

    ull acc2[8][4];
#pragma unroll
    for (int i = 0; i < 8; i++)
#pragma unroll
        for (int j = 0; j < 4; j++) acc2[i][j] = 0ull;

    auto issue_loads = [&](int it, int buf) {
        int k0 = it * BKK;
#pragma unroll
        for (int p = 0; p < 8; p++) {
            int kk = k0 + ka;
            int m  = ra + p * 16;
            int row = block_m + m;
            if (kk < KI) {
                unsigned int dst =
                    (unsigned int)__cvta_generic_to_shared(&As[buf][ka][m]);
                cpa4(dst, x + (size_t)row * KI + kk);
            } else {
                As[buf][ka][m] = 0.f;
            }
        }
#pragma unroll
        for (int q = 0; q < 2; q++) {
            int r = brow + q * 8;
            int kk = k0 + r;
            if (kk < KI) {
                unsigned int dst =
                    (unsigned int)__cvta_generic_to_shared(&Bs[buf][r][bcol4 * 4]);
                cpa16(dst, w + (size_t)kk * H + bcol4 * 4);
            } else {
                *(float4*)&Bs[buf][r][bcol4 * 4] = make_float4(0.f, 0.f, 0.f, 0.f);
            }
        }
        cpa_commit();
    };

    issue_loads(0, 0);

    for (int it = 0; it < NT; it++) {
        cpa_wait_all();
        __syncthreads();
        const int cur = it & 1;
        if (it + 1 < NT) issue_loads(it + 1, cur ^ 1);

#pragma unroll
        for (int k = 0; k < BKK; k++) {
            const float4* ap = (const float4*)&As[cur][k][tm * 8];
            const float4* bp = (const float4*)&Bs[cur][k][tn * 8];
            float4 a0 = ap[0], a1 = ap[1];
            float4 b0 = bp[0], b1 = bp[1];
            ull bp0 = pk2(b0.x, b0.y);
            ull bp1 = pk2(b0.z, b0.w);
            ull bp2 = pk2(b1.x, b1.y);
            ull bp3 = pk2(b1.z, b1.w);
            float av[8];
            av[0]=a0.x; av[1]=a0.y; av[2]=a0.z; av[3]=a0.w;
            av[4]=a1.x; av[5]=a1.y; av[6]=a1.z; av[7]=a1.w;
#pragma unroll
            for (int i = 0; i < 8; i++) {
                ull apk = pk2(av[i], av[i]);
                ffma2(acc2[i][0], apk, bp0);
                ffma2(acc2[i][1], apk, bp1);
                ffma2(acc2[i][2], apk, bp2);
                ffma2(acc2[i][3], apk, bp3);
            }
        }
    }

#pragma unroll
    for (int i = 0; i < 8; i++) {
        int row = block_m + tm * 8 + i;
#pragma unroll
        for (int jp = 0; jp < 4; jp++) {
            float lo, hi;
            upk2(lo, hi, acc2[i][jp]);
            int col = tn * 8 + 2 * jp;
            g_xin[(size_t)row * H + col]     = __fadd_rn(lo, bias[col]);
            g_xin[(size_t)row * H + col + 1] = __fadd_rn(hi, bias[col + 1]);
        }
    }
}

// ---------------------------------------------------------------------------
// Phase 2: scan. SMEM layout (float offsets):
//   WPACK [0, 32768)     float2 wp2[h*128+g] = {w12[h][g], w22m[h][g]}
//   WOS   [32768, 35328) w_h2o
//   SPAIR [35328, 36352) [2grp][2buf][128] float2 {s1, s2prev}
//   MKH   [36352, 38352) [2grp][250][4] u32 layer-2 ballots
//   OBUF  [38352, 48352) [2grp][250][20] io -> om -> softmax (in place)
// Total 48352 floats = 193408 bytes -> 1 block/SM, 128 blocks.
// ---------------------------------------------------------------------------
#define WPACKO 0
#define WOSO   32768
#define SPAIRO 35328
#define MKHO   36352
#define OBUFO  38352
#define SCAN_SMEM_BYTES (48352 * 4)

__global__ __launch_bounds__(256, 1)
void snn_scan_kernel(const float* __restrict__ mask,
                     const float* __restrict__ w11g, const float* __restrict__ b11g,
                     const float* __restrict__ w12g, const float* __restrict__ b12g,
                     const float* __restrict__ w22g, const float* __restrict__ b22g,
                     const float* __restrict__ wog,  const float* __restrict__ bog,
                     const float* __restrict__ tau_adp1, const float* __restrict__ tau_adp2,
                     const float* __restrict__ tau_m1,   const float* __restrict__ tau_m2,
                     const float* __restrict__ tau_mo,
                     const float* __restrict__ h1m0, const float* __restrict__ h2m0,
                     const float* __restrict__ om0,
                     float* __restrict__ out_acc,
                     float* __restrict__ out_s1,
                     float* __restrict__ out_s2)
{
    extern __shared__ float smf[];
    float2*   wp2  = (float2*)(smf + WPACKO);
    float*    wos  = smf + WOSO;

    const int tid  = threadIdx.x;
    const int g    = tid & (H - 1);
    const int grp  = tid >> 7;
    const int b    = blockIdx.x * 2 + grp;
    const int lane = tid & 31;
    const int wig  = g >> 5;
    const int barid = grp + 1;

    float2*   spb  = (float2*)(smf + SPAIRO) + grp * 256;   // [buf][128]
    unsigned* mkh  = (unsigned*)(smf + MKHO) + grp * (TT * 4);
    float*    obuf = smf + OBUFO + grp * (TT * OO);

    // Weight staging: packed (w12, w22*mask1) pairs + readout weights
    for (int i = tid; i < H * H; i += blockDim.x)
        wp2[i] = make_float2(w12g[i], __fmul_rn(w22g[i], mask[H * H + i]));
    for (int i = tid; i < H * OO; i += blockDim.x) wos[i] = wog[i];
    __syncthreads();

    // W11 column g register-resident
    float w11r[H];
#pragma unroll
    for (int hp = 0; hp < H; hp++)
        w11r[hp] = __fmul_rn(w11g[hp * H + g], mask[hp * H + g]);

    const float a1    = xla_expf(__fdiv_rn(-1.f, tau_m1[g]));
    const float r1    = xla_expf(__fdiv_rn(-1.f, tau_adp1[g]));
    const float a2    = xla_expf(__fdiv_rn(-1.f, tau_m2[g]));
    const float r2    = xla_expf(__fdiv_rn(-1.f, tau_adp2[g]));
    const float om_a1 = __fsub_rn(1.f, a1);
    const float om_r1 = __fsub_rn(1.f, r1);
    const float om_a2 = __fsub_rn(1.f, a2);
    const float om_r2 = __fsub_rn(1.f, r2);
    const float bi1 = b11g[g];
    const float b12 = b12g[g];
    const float b22 = b22g[g];

    float h1m = h1m0[b * H + g];
    float h2m = h2m0[b * H + g];
    float bb1 = 0.01f, bb2 = 0.01f;
    float spk1 = 0.f, spk2 = 0.f;
    float s1c = 0.f, s2c = 0.f;
    float d1cur = 0.f;

    const float* xrow = g_xin + (size_t)b * TT * H + g;
    float xt_cur = xrow[0];

#pragma unroll 1
    for (int t = 0; t < TT; t++) {
        const int pb = t & 1;
        float xt_next = (t + 1 < TT) ? xrow[(size_t)(t + 1) * H] : 0.f;

        // ---- layer 1 elementwise (uses d1cur computed last iteration) ----
        float i1 = __fadd_rn(__fadd_rn(xt_cur, d1cur), bi1);
        bb1 = __fadd_rn(__fmul_rn(r1, bb1), __fmul_rn(om_r1, spk1));
        float B1 = __fadd_rn(0.01f, __fmul_rn(1.8f, bb1));
        h1m = __fsub_rn(__fadd_rn(__fmul_rn(h1m, a1), __fmul_rn(om_a1, i1)),
                        __fmul_rn(B1, spk1));
        float ns1 = (__fsub_rn(h1m, B1) > 0.f) ? 1.f : 0.f;
        s1c = __fadd_rn(s1c, ns1);
        spk1 = ns1;
        // publish (s1(t), s2(t-1)) pair for this neuron
        spb[pb * H + g] = make_float2(ns1, spk2);
        asm volatile("bar.sync %0, %1;" :: "r"(barid), "r"(128) : "memory");

        // ---- fused triple chain: d12(t) & d22(t) packed, d1(t+1) scalar ----
        ull acc2 = 0ull;
        float d1n = 0.f;
        const float4* sp4 = (const float4*)(spb + pb * H);
#pragma unroll
        for (int c = 0; c < 64; c++) {
            float4 sv = sp4[c];   // {s1[2c], s2[2c], s1[2c+1], s2[2c+1]}
            ull w01 = *(const ull*)(wp2 + (2 * c) * H + g);
            ull w23 = *(const ull*)(wp2 + (2 * c + 1) * H + g);
            ffma2(acc2, pk2(sv.x, sv.y), w01);
            d1n = fmaf(sv.x, w11r[2 * c], d1n);
            ffma2(acc2, pk2(sv.z, sv.w), w23);
            d1n = fmaf(sv.z, w11r[2 * c + 1], d1n);
        }
        float d12, d22;
        upk2(d12, d22, acc2);

        // ---- layer 2 elementwise ----
        float i2 = __fadd_rn(__fadd_rn(__fadd_rn(d12, b12), d22), b22);
        bb2 = __fadd_rn(__fmul_rn(r2, bb2), __fmul_rn(om_r2, spk2));
        float B2 = __fadd_rn(0.01f, __fmul_rn(1.8f, bb2));
        h2m = __fsub_rn(__fadd_rn(__fmul_rn(h2m, a2), __fmul_rn(om_a2, i2)),
                        __fmul_rn(B2, spk2));
        float ns2 = (__fsub_rn(h2m, B2) > 0.f) ? 1.f : 0.f;
        s2c = __fadd_rn(s2c, ns2);
        spk2 = ns2;
        unsigned bal = __ballot_sync(0xffffffffu, ns2 != 0.f);
        if (lane == 0) mkh[t * 4 + wig] = bal;

        d1cur = d1n;
        xt_cur = xt_next;
    }

    asm volatile("bar.sync %0, %1;" :: "r"(barid), "r"(128) : "memory");

    // ---- P1: io(t,o) = asc-chain(s2(t) * w_h2o[:,o]) + b_h2o[o] ----
    for (int idx = g; idx < TT * OO; idx += H) {
        int t = idx / OO;
        int o = idx - t * OO;
        const unsigned* mh = mkh + t * 4;
        float io = 0.f;
#pragma unroll
        for (int w4 = 0; w4 < 4; w4++) {
            unsigned m = mh[w4];
            const float* wb = wos + (w4 * 32) * OO + o;
#pragma unroll
            for (int hb = 0; hb < 32; hb++) {
                if (m & 1u) io = __fadd_rn(io, wb[hb * OO]);
                m >>= 1;
            }
        }
        io = __fadd_rn(io, bog[o]);
        obuf[idx] = io;
    }
    asm volatile("bar.sync %0, %1;" :: "r"(barid), "r"(128) : "memory");

    // ---- P2: om recurrence (serial in t, parallel in o) ----
    if (g < OO) {
        float omv    = om0[b * OO + g];
        float aov    = xla_expf(__fdiv_rn(-1.f, tau_mo[g]));
        float om_aov = __fsub_rn(1.f, aov);
#pragma unroll 1
        for (int t = 0; t < TT; t++) {
            omv = __fadd_rn(__fmul_rn(omv, aov),
                            __fmul_rn(om_aov, obuf[t * OO + g]));
            obuf[t * OO + g] = omv;
        }
    }
    asm volatile("bar.sync %0, %1;" :: "r"(barid), "r"(128) : "memory");

    // ---- P3: softmax per t (parallel over t), in place ----
    for (int t = g; t < TT; t += H) {
        if (t > 10) {
            float* r = obuf + t * OO;
            float mx = r[0];
#pragma unroll
            for (int j = 1; j < OO; j++) mx = fmaxf(mx, r[j]);
            float ev[OO];
            float ssum = 0.f;
#pragma unroll
            for (int j = 0; j < OO; j++) {
                ev[j] = xla_expf(__fsub_rn(r[j], mx));
                ssum = __fadd_rn(ssum, ev[j]);
            }
#pragma unroll
            for (int j = 0; j < OO; j++) r[j] = __fdiv_rn(ev[j], ssum);
        }
    }
    asm volatile("bar.sync %0, %1;" :: "r"(barid), "r"(128) : "memory");

    // ---- P4: acc = ascending-t sum of softmax (t>10), per output ----
    if (g < OO) {
        float acc = 0.f;
#pragma unroll 1
        for (int t = 11; t < TT; t++)
            acc = __fadd_rn(acc, obuf[t * OO + g]);
        out_acc[b * OO + g] = acc;
    }

    out_s1[b * H + g] = __fdiv_rn(s1c, 250.f);
    out_s2[b * H + g] = __fdiv_rn(s2c, 250.f);
}

// ---------------------------------------------------------------------------
// A_norm = sum |w_h1h1 * mask0| + sum |w_h2h2 * mask1|
// ---------------------------------------------------------------------------
__global__ void anorm_kernel(const float* __restrict__ w11g,
                             const float* __restrict__ w22g,
                             const float* __restrict__ mask,
                             float* __restrict__ out)
{
    __shared__ float red[256];
    float s1 = 0.f, s2 = 0.f;
    for (int i = threadIdx.x; i < H * H; i += 256) {
        s1 = __fadd_rn(s1, fabsf(__fmul_rn(w11g[i], mask[i])));
        s2 = __fadd_rn(s2, fabsf(__fmul_rn(w22g[i], mask[H * H + i])));
    }
    red[threadIdx.x] = __fadd_rn(s1, s2);
    __syncthreads();
    for (int st = 128; st; st >>= 1) {
        if (threadIdx.x < st)
            red[threadIdx.x] = __fadd_rn(red[threadIdx.x], red[threadIdx.x + st]);
        __syncthreads();
    }
    if (threadIdx.x == 0) out[0] = red[0];
}

// ---------------------------------------------------------------------------
extern "C" void kernel_launch(void* const* d_in, const int* in_sizes, int n_in,
                              void* d_out, int out_size)
{
    const float* x          = (const float*)d_in[0];
    const float* mask       = (const float*)d_in[1];
    const float* w_ih1      = (const float*)d_in[2];
    const float* b_ih1      = (const float*)d_in[3];
    const float* w_h1h1     = (const float*)d_in[4];
    const float* b_h1h1     = (const float*)d_in[5];
    const float* w_h1h2     = (const float*)d_in[6];
    const float* b_h1h2     = (const float*)d_in[7];
    const float* w_h2h2     = (const float*)d_in[8];
    const float* b_h2h2     = (const float*)d_in[9];
    const float* w_h2o      = (const float*)d_in[10];
    const float* b_h2o      = (const float*)d_in[11];
    const float* tau_adp_h1 = (const float*)d_in[12];
    const float* tau_adp_h2 = (const float*)d_in[13];
    const float* tau_m_h1   = (const float*)d_in[14];
    const float* tau_m_h2   = (const float*)d_in[15];
    const float* tau_m_o    = (const float*)d_in[16];
    const float* h1m0       = (const float*)d_in[17];
    const float* h2m0       = (const float*)d_in[18];
    const float* om0        = (const float*)d_in[19];

    float* out = (float*)d_out;
    float* out_acc = out;
    float* out_s1  = out + BB * OO;
    float* out_s2  = out + BB * OO + BB * H;
    float* out_an  = out + BB * OO + 2 * BB * H;

    cudaFuncSetAttribute(snn_scan_kernel,
                         cudaFuncAttributeMaxDynamicSharedMemorySize,
                         SCAN_SMEM_BYTES);

    gemm_xin_kernel<<<MTOT / BM, 256>>>(x, w_ih1, b_ih1);

    snn_scan_kernel<<<BB / 2, 256, SCAN_SMEM_BYTES>>>(
        mask,
        w_h1h1, b_h1h1, w_h1h2, b_h1h2, w_h2h2, b_h2h2, w_h2o, b_h2o,
        tau_adp_h1, tau_adp_h2, tau_m_h1, tau_m_h2, tau_m_o,
        h1m0, h2m0, om0,
        out_acc, out_s1, out_s2);

    anorm_kernel<<<1, 256>>>(w_h1h1, w_h2h2, mask, out_an);
}

// round 12
// speedup vs baseline: 1.0545x; 1.0545x over previous
#include <cuda_runtime.h>
#include <stdint.h>
#include <math.h>

// Problem constants (fixed by the dataset)
#define H   128
#define OO  20
#define KI  700
#define BB  256
#define TT  250
#define MTOT (BB * TT)   // 64000

// Scratch for the hoisted input projection: xin[(b*T + t)][h]
__device__ float g_xin[(size_t)MTOT * H];

// ---------------------------------------------------------------------------
// f32x2 packed helpers (sm_103a). fma.rn.f32x2 = two independent rn fp32 FMAs
// in one fma-pipe instruction -> bitwise identical to two fmaf.
// ---------------------------------------------------------------------------
typedef unsigned long long ull;

__device__ __forceinline__ ull pk2(float lo, float hi) {
    ull r;
    asm("mov.b64 %0, {%1, %2};" : "=l"(r) : "f"(lo), "f"(hi));
    return r;
}
__device__ __forceinline__ void upk2(float& lo, float& hi, ull v) {
    asm("mov.b64 {%0, %1}, %2;" : "=f"(lo), "=f"(hi) : "l"(v));
}
__device__ __forceinline__ void ffma2(ull& acc, ull a, ull b) {
    asm("fma.rn.f32x2 %0, %1, %2, %0;" : "+l"(acc) : "l"(a), "l"(b));
}

// cp.async wrappers
__device__ __forceinline__ void cpa4(unsigned int dst, const void* src) {
    asm volatile("cp.async.ca.shared.global [%0], [%1], 4;" :: "r"(dst), "l"(src));
}
__device__ __forceinline__ void cpa16(unsigned int dst, const void* src) {
    asm volatile("cp.async.cg.shared.global [%0], [%1], 16;" :: "r"(dst), "l"(src));
}
__device__ __forceinline__ void cpa_commit() {
    asm volatile("cp.async.commit_group;");
}
__device__ __forceinline__ void cpa_wait_1() {
    asm volatile("cp.async.wait_group 1;");
}

// ---------------------------------------------------------------------------
// Bit-exact transcription of XLA CPU's vectorized expf (Cephes/Eigen pexp).
// ---------------------------------------------------------------------------
__device__ __forceinline__ float xla_expf(float xin_) {
    const float exp_hi = 88.3762626647950f;
    const float exp_lo = -88.3762626647949f;
    const float LOG2EF = 1.44269504088896341f;
    const float C1 = 0.693359375f;
    const float C2 = -2.12194440e-4f;
    const float p0 = 1.9875691500E-4f;
    const float p1 = 1.3981999507E-3f;
    const float p2 = 8.3334519073E-3f;
    const float p3 = 4.1665795894E-2f;
    const float p4 = 1.6666665459E-1f;
    const float p5 = 5.0000001201E-1f;

    float x = fminf(fmaxf(xin_, exp_lo), exp_hi);
    float fx = floorf(__fadd_rn(__fmul_rn(x, LOG2EF), 0.5f));
    float tmp = __fmul_rn(C1, fx);
    float z   = __fmul_rn(C2, fx);
    float xx  = __fsub_rn(x, tmp);
    xx = __fsub_rn(xx, z);
    z = __fmul_rn(xx, xx);
    float y = __fadd_rn(__fmul_rn(xx, p0), p1);
    y = __fadd_rn(__fmul_rn(y, xx), p2);
    y = __fadd_rn(__fmul_rn(y, xx), p3);
    y = __fadd_rn(__fmul_rn(y, xx), p4);
    y = __fadd_rn(__fmul_rn(y, xx), p5);
    y = __fadd_rn(__fmul_rn(y, z), xx);
    y = __fadd_rn(1.0f, y);
    int n = (int)fx;
    float p2n = __int_as_float((n + 127) << 23);
    float r = __fmul_rn(y, p2n);
    return fmaxf(r, xin_);
}

// ---------------------------------------------------------------------------
// Phase 1: xin = x @ w_ih1 + b_ih1   (M=64000, K=700, N=128, strict fp32)
// 256 threads, 128x128 tile, 8x8 micro-tile, 3-stage cp.async pipeline
// (issue-to-use distance 2 tiles > DRAM latency), FFMA2, 2 blocks/SM.
// Ascending-k FMA chain per output — bit-identical to prior rounds.
// ---------------------------------------------------------------------------
#define BM  128
#define BN  128
#define BKK 16
#define NT  44
#define ASTRIDE (BM + 4)
#define STG 3

__global__ __launch_bounds__(256, 2)
void gemm_xin_kernel(const float* __restrict__ x,
                     const float* __restrict__ w,
                     const float* __restrict__ bias)
{
    __shared__ float As[STG][BKK][ASTRIDE];
    __shared__ float Bs[STG][BKK][BN];

    const int tid     = threadIdx.x;
    const int block_m = blockIdx.x * BM;
    const int tn      = tid & 15;
    const int tm      = tid >> 4;

    const int ka = tid & 15, ra = tid >> 4;
    const int brow = tid >> 5, bcol4 = tid & 31;

    ull acc2[8][4];
#pragma unroll
    for (int i = 0; i < 8; i++)
#pragma unroll
        for (int j = 0; j < 4; j++) acc2[i][j] = 0ull;

    auto issue_loads = [&](int it, int buf) {
        int k0 = it * BKK;
#pragma unroll
        for (int p = 0; p < 8; p++) {
            int kk = k0 + ka;
            int m  = ra + p * 16;
            int row = block_m + m;
            if (kk < KI) {
                unsigned int dst =
                    (unsigned int)__cvta_generic_to_shared(&As[buf][ka][m]);
                cpa4(dst, x + (size_t)row * KI + kk);
            } else {
                As[buf][ka][m] = 0.f;
            }
        }
#pragma unroll
        for (int q = 0; q < 2; q++) {
            int r = brow + q * 8;
            int kk = k0 + r;
            if (kk < KI) {
                unsigned int dst =
                    (unsigned int)__cvta_generic_to_shared(&Bs[buf][r][bcol4 * 4]);
                cpa16(dst, w + (size_t)kk * H + bcol4 * 4);
            } else {
                *(float4*)&Bs[buf][r][bcol4 * 4] = make_float4(0.f, 0.f, 0.f, 0.f);
            }
        }
        cpa_commit();
    };

    issue_loads(0, 0);
    issue_loads(1, 1);

    for (int it = 0; it < NT; it++) {
        cpa_wait_1();            // oldest outstanding group (tile it) complete
        __syncthreads();
        if (it + 2 < NT) issue_loads(it + 2, (it + 2) % STG);
        else             cpa_commit();   // empty group keeps wait_1 semantics uniform
        const int cur = it % STG;

#pragma unroll
        for (int k = 0; k < BKK; k++) {
            const float4* ap = (const float4*)&As[cur][k][tm * 8];
            const float4* bp = (const float4*)&Bs[cur][k][tn * 8];
            float4 a0 = ap[0], a1 = ap[1];
            float4 b0 = bp[0], b1 = bp[1];
            ull bp0 = pk2(b0.x, b0.y);
            ull bp1 = pk2(b0.z, b0.w);
            ull bp2 = pk2(b1.x, b1.y);
            ull bp3 = pk2(b1.z, b1.w);
            float av[8];
            av[0]=a0.x; av[1]=a0.y; av[2]=a0.z; av[3]=a0.w;
            av[4]=a1.x; av[5]=a1.y; av[6]=a1.z; av[7]=a1.w;
#pragma unroll
            for (int i = 0; i < 8; i++) {
                ull apk = pk2(av[i], av[i]);
                ffma2(acc2[i][0], apk, bp0);
                ffma2(acc2[i][1], apk, bp1);
                ffma2(acc2[i][2], apk, bp2);
                ffma2(acc2[i][3], apk, bp3);
            }
        }
    }

#pragma unroll
    for (int i = 0; i < 8; i++) {
        int row = block_m + tm * 8 + i;
#pragma unroll
        for (int jp = 0; jp < 4; jp++) {
            float lo, hi;
            upk2(lo, hi, acc2[i][jp]);
            int col = tn * 8 + 2 * jp;
            g_xin[(size_t)row * H + col]     = __fadd_rn(lo, bias[col]);
            g_xin[(size_t)row * H + col + 1] = __fadd_rn(hi, bias[col + 1]);
        }
    }
}

// ---------------------------------------------------------------------------
// Phase 2: scan. ONE 128-thread block handles TWO batch elements: each
// packed weight read (w12,w22m) is applied to both batches' chains, halving
// smem crossbar traffic per SM. All chains keep exact ascending order.
// SMEM layout (float offsets):
//   WPACK [0, 32768)     float2 wp2[h*128+g] = {w12[h][g], w22m[h][g]}
//   WOS   [32768, 35328) w_h2o
//   SPAIR [35328, 36352) [2buf][2batch][128] float2 {s1, s2prev}
//   MKH   [36352, 38352) [2batch][250][4] u32 layer-2 ballots
//   OBUF  [38352, 48352) [2batch][250][20] io -> om -> softmax (in place)
// Total 48352 floats = 193408 bytes -> 1 block/SM, 128 blocks.
// ---------------------------------------------------------------------------
#define WPACKO 0
#define WOSO   32768
#define SPAIRO 35328
#define MKHO   36352
#define OBUFO  38352
#define SCAN_SMEM_BYTES (48352 * 4)

__global__ __launch_bounds__(128, 1)
void snn_scan_kernel(const float* __restrict__ mask,
                     const float* __restrict__ w11g, const float* __restrict__ b11g,
                     const float* __restrict__ w12g, const float* __restrict__ b12g,
                     const float* __restrict__ w22g, const float* __restrict__ b22g,
                     const float* __restrict__ wog,  const float* __restrict__ bog,
                     const float* __restrict__ tau_adp1, const float* __restrict__ tau_adp2,
                     const float* __restrict__ tau_m1,   const float* __restrict__ tau_m2,
                     const float* __restrict__ tau_mo,
                     const float* __restrict__ h1m0, const float* __restrict__ h2m0,
                     const float* __restrict__ om0,
                     float* __restrict__ out_acc,
                     float* __restrict__ out_s1,
                     float* __restrict__ out_s2)
{
    extern __shared__ float smf[];
    float2*   wp2  = (float2*)(smf + WPACKO);
    float*    wos  = smf + WOSO;
    float2*   spb  = (float2*)(smf + SPAIRO);       // [buf][batch][128]
    unsigned* mkh  = (unsigned*)(smf + MKHO);       // [batch][250][4]
    float*    obuf = smf + OBUFO;                   // [batch][250][20]

    const int g    = threadIdx.x;       // neuron index (0..127)
    const int lane = g & 31;
    const int wig  = g >> 5;
    const int b0   = blockIdx.x * 2;

    // Weight staging: packed (w12, w22*mask1) pairs + readout weights
    for (int i = g; i < H * H; i += H)
        wp2[i] = make_float2(w12g[i], __fmul_rn(w22g[i], mask[H * H + i]));
    for (int i = g; i < H * OO; i += H) wos[i] = wog[i];
    __syncthreads();

    // W11 column g register-resident (shared across both batches)
    float w11r[H];
#pragma unroll
    for (int hp = 0; hp < H; hp++)
        w11r[hp] = __fmul_rn(w11g[hp * H + g], mask[hp * H + g]);

    const float a1    = xla_expf(__fdiv_rn(-1.f, tau_m1[g]));
    const float r1    = xla_expf(__fdiv_rn(-1.f, tau_adp1[g]));
    const float a2    = xla_expf(__fdiv_rn(-1.f, tau_m2[g]));
    const float r2    = xla_expf(__fdiv_rn(-1.f, tau_adp2[g]));
    const float om_a1 = __fsub_rn(1.f, a1);
    const float om_r1 = __fsub_rn(1.f, r1);
    const float om_a2 = __fsub_rn(1.f, a2);
    const float om_r2 = __fsub_rn(1.f, r2);
    const float bi1 = b11g[g];
    const float b12 = b12g[g];
    const float b22 = b22g[g];

    float h1m[2], h2m[2], bb1[2], bb2[2], spk1[2], spk2[2];
    float s1c[2], s2c[2], d1cur[2], xt_cur[2];
    const float* xrow[2];
#pragma unroll
    for (int nb = 0; nb < 2; nb++) {
        int b = b0 + nb;
        h1m[nb]  = h1m0[b * H + g];
        h2m[nb]  = h2m0[b * H + g];
        bb1[nb]  = 0.01f; bb2[nb] = 0.01f;
        spk1[nb] = 0.f;   spk2[nb] = 0.f;
        s1c[nb]  = 0.f;   s2c[nb] = 0.f;
        d1cur[nb] = 0.f;
        xrow[nb] = g_xin + (size_t)b * TT * H + g;
        xt_cur[nb] = xrow[nb][0];
    }

#pragma unroll 1
    for (int t = 0; t < TT; t++) {
        const int pb = t & 1;
        float xt_next[2];
#pragma unroll
        for (int nb = 0; nb < 2; nb++)
            xt_next[nb] = (t + 1 < TT) ? xrow[nb][(size_t)(t + 1) * H] : 0.f;

        // ---- layer 1 elementwise (uses d1cur from previous chain pass) ----
#pragma unroll
        for (int nb = 0; nb < 2; nb++) {
            float i1 = __fadd_rn(__fadd_rn(xt_cur[nb], d1cur[nb]), bi1);
            bb1[nb] = __fadd_rn(__fmul_rn(r1, bb1[nb]), __fmul_rn(om_r1, spk1[nb]));
            float B1 = __fadd_rn(0.01f, __fmul_rn(1.8f, bb1[nb]));
            h1m[nb] = __fsub_rn(__fadd_rn(__fmul_rn(h1m[nb], a1), __fmul_rn(om_a1, i1)),
                                __fmul_rn(B1, spk1[nb]));
            float ns1 = (__fsub_rn(h1m[nb], B1) > 0.f) ? 1.f : 0.f;
            s1c[nb] = __fadd_rn(s1c[nb], ns1);
            spk1[nb] = ns1;
            spb[(pb * 2 + nb) * H + g] = make_float2(ns1, spk2[nb]);
        }
        __syncthreads();

        // ---- fused chains: d12/d22 packed + d1(t+1), both batches,
        //      ONE weight read serves both batches ----
        ull accA = 0ull, accB = 0ull;
        float d1nA = 0.f, d1nB = 0.f;
        const float4* spA = (const float4*)(spb + (pb * 2 + 0) * H);
        const float4* spB = (const float4*)(spb + (pb * 2 + 1) * H);
#pragma unroll
        for (int c = 0; c < 64; c++) {
            float4 sa = spA[c];   // {s1[2c], s2[2c], s1[2c+1], s2[2c+1]} batch0
            float4 sb = spB[c];   // batch1
            ull w01 = *(const ull*)(wp2 + (2 * c) * H + g);
            ull w23 = *(const ull*)(wp2 + (2 * c + 1) * H + g);
            ffma2(accA, pk2(sa.x, sa.y), w01);
            ffma2(accB, pk2(sb.x, sb.y), w01);
            d1nA = fmaf(sa.x, w11r[2 * c], d1nA);
            d1nB = fmaf(sb.x, w11r[2 * c], d1nB);
            ffma2(accA, pk2(sa.z, sa.w), w23);
            ffma2(accB, pk2(sb.z, sb.w), w23);
            d1nA = fmaf(sa.z, w11r[2 * c + 1], d1nA);
            d1nB = fmaf(sb.z, w11r[2 * c + 1], d1nB);
        }

        // ---- layer 2 elementwise + ballots ----
#pragma unroll
        for (int nb = 0; nb < 2; nb++) {
            float d12, d22;
            upk2(d12, d22, nb ? accB : accA);
            float i2 = __fadd_rn(__fadd_rn(__fadd_rn(d12, b12), d22), b22);
            bb2[nb] = __fadd_rn(__fmul_rn(r2, bb2[nb]), __fmul_rn(om_r2, spk2[nb]));
            float B2 = __fadd_rn(0.01f, __fmul_rn(1.8f, bb2[nb]));
            h2m[nb] = __fsub_rn(__fadd_rn(__fmul_rn(h2m[nb], a2), __fmul_rn(om_a2, i2)),
                                __fmul_rn(B2, spk2[nb]));
            float ns2 = (__fsub_rn(h2m[nb], B2) > 0.f) ? 1.f : 0.f;
            s2c[nb] = __fadd_rn(s2c[nb], ns2);
            spk2[nb] = ns2;
            unsigned bal = __ballot_sync(0xffffffffu, ns2 != 0.f);
            if (lane == 0) mkh[(nb * TT + t) * 4 + wig] = bal;
        }

        d1cur[0] = d1nA; d1cur[1] = d1nB;
        xt_cur[0] = xt_next[0]; xt_cur[1] = xt_next[1];
    }

    __syncthreads();

    // ---- P1: io(nb,t,o) = asc-chain(s2(t) * w_h2o[:,o]) + b_h2o[o] ----
    for (int idx = g; idx < 2 * TT * OO; idx += H) {
        int nb = idx / (TT * OO);
        int rem = idx - nb * (TT * OO);
        int t = rem / OO;
        int o = rem - t * OO;
        const unsigned* mh = mkh + (nb * TT + t) * 4;
        float io = 0.f;
#pragma unroll
        for (int w4 = 0; w4 < 4; w4++) {
            unsigned m = mh[w4];
            const float* wb = wos + (w4 * 32) * OO + o;
#pragma unroll
            for (int hb = 0; hb < 32; hb++) {
                if (m & 1u) io = __fadd_rn(io, wb[hb * OO]);
                m >>= 1;
            }
        }
        io = __fadd_rn(io, bog[o]);
        obuf[idx] = io;
    }
    __syncthreads();

    // ---- P2: om recurrence (serial in t; parallel over 2x20 channels) ----
    if (g < 2 * OO) {
        int nb = g / OO;
        int o  = g - nb * OO;
        float omv    = om0[(b0 + nb) * OO + o];
        float aov    = xla_expf(__fdiv_rn(-1.f, tau_mo[o]));
        float om_aov = __fsub_rn(1.f, aov);
        float* ob = obuf + nb * (TT * OO) + o;
#pragma unroll 1
        for (int t = 0; t < TT; t++) {
            omv = __fadd_rn(__fmul_rn(omv, aov), __fmul_rn(om_aov, ob[t * OO]));
            ob[t * OO] = omv;
        }
    }
    __syncthreads();

    // ---- P3: softmax per (nb,t), in place ----
    for (int idx = g; idx < 2 * TT; idx += H) {
        int nb = idx / TT;
        int t  = idx - nb * TT;
        if (t > 10) {
            float* r = obuf + (nb * TT + t) * OO;
            float mx = r[0];
#pragma unroll
            for (int j = 1; j < OO; j++) mx = fmaxf(mx, r[j]);
            float ev[OO];
            float ssum = 0.f;
#pragma unroll
            for (int j = 0; j < OO; j++) {
                ev[j] = xla_expf(__fsub_rn(r[j], mx));
                ssum = __fadd_rn(ssum, ev[j]);
            }
#pragma unroll
            for (int j = 0; j < OO; j++) r[j] = __fdiv_rn(ev[j], ssum);
        }
    }
    __syncthreads();

    // ---- P4: acc = ascending-t sum of softmax (t>10) ----
    if (g < 2 * OO) {
        int nb = g / OO;
        int o  = g - nb * OO;
        const float* ob = obuf + nb * (TT * OO) + o;
        float acc = 0.f;
#pragma unroll 1
        for (int t = 11; t < TT; t++)
            acc = __fadd_rn(acc, ob[t * OO]);
        out_acc[(b0 + nb) * OO + o] = acc;
    }

#pragma unroll
    for (int nb = 0; nb < 2; nb++) {
        out_s1[(b0 + nb) * H + g] = __fdiv_rn(s1c[nb], 250.f);
        out_s2[(b0 + nb) * H + g] = __fdiv_rn(s2c[nb], 250.f);
    }
}

// ---------------------------------------------------------------------------
// A_norm = sum |w_h1h1 * mask0| + sum |w_h2h2 * mask1|
// ---------------------------------------------------------------------------
__global__ void anorm_kernel(const float* __restrict__ w11g,
                             const float* __restrict__ w22g,
                             const float* __restrict__ mask,
                             float* __restrict__ out)
{
    __shared__ float red[256];
    float s1 = 0.f, s2 = 0.f;
    for (int i = threadIdx.x; i < H * H; i += 256) {
        s1 = __fadd_rn(s1, fabsf(__fmul_rn(w11g[i], mask[i])));
        s2 = __fadd_rn(s2, fabsf(__fmul_rn(w22g[i], mask[H * H + i])));
    }
    red[threadIdx.x] = __fadd_rn(s1, s2);
    __syncthreads();
    for (int st = 128; st; st >>= 1) {
        if (threadIdx.x < st)
            red[threadIdx.x] = __fadd_rn(red[threadIdx.x], red[threadIdx.x + st]);
        __syncthreads();
    }
    if (threadIdx.x == 0) out[0] = red[0];
}

// ---------------------------------------------------------------------------
extern "C" void kernel_launch(void* const* d_in, const int* in_sizes, int n_in,
                              void* d_out, int out_size)
{
    const float* x          = (const float*)d_in[0];
    const float* mask       = (const float*)d_in[1];
    const float* w_ih1      = (const float*)d_in[2];
    const float* b_ih1      = (const float*)d_in[3];
    const float* w_h1h1     = (const float*)d_in[4];
    const float* b_h1h1     = (const float*)d_in[5];
    const float* w_h1h2     = (const float*)d_in[6];
    const float* b_h1h2     = (const float*)d_in[7];
    const float* w_h2h2     = (const float*)d_in[8];
    const float* b_h2h2     = (const float*)d_in[9];
    const float* w_h2o      = (const float*)d_in[10];
    const float* b_h2o      = (const float*)d_in[11];
    const float* tau_adp_h1 = (const float*)d_in[12];
    const float* tau_adp_h2 = (const float*)d_in[13];
    const float* tau_m_h1   = (const float*)d_in[14];
    const float* tau_m_h2   = (const float*)d_in[15];
    const float* tau_m_o    = (const float*)d_in[16];
    const float* h1m0       = (const float*)d_in[17];
    const float* h2m0       = (const float*)d_in[18];
    const float* om0        = (const float*)d_in[19];

    float* out = (float*)d_out;
    float* out_acc = out;
    float* out_s1  = out + BB * OO;
    float* out_s2  = out + BB * OO + BB * H;
    float* out_an  = out + BB * OO + 2 * BB * H;

    cudaFuncSetAttribute(snn_scan_kernel,
                         cudaFuncAttributeMaxDynamicSharedMemorySize,
                         SCAN_SMEM_BYTES);

    gemm_xin_kernel<<<MTOT / BM, 256>>>(x, w_ih1, b_ih1);

    snn_scan_kernel<<<BB / 2, 128, SCAN_SMEM_BYTES>>>(
        mask,
        w_h1h1, b_h1h1, w_h1h2, b_h1h2, w_h2h2, b_h2h2, w_h2o, b_h2o,
        tau_adp_h1, tau_adp_h2, tau_m_h1, tau_m_h2, tau_m_o,
        h1m0, h2m0, om0,
        out_acc, out_s1, out_s2);

    anorm_kernel<<<1, 256>>>(w_h1h1, w_h2h2, mask, out_an);
}